// round 4
// baseline (speedup 1.0000x reference)
#include <cuda_runtime.h>
#include <cuda_bf16.h>
#include <math.h>

// Problem constants (RotatEDecoder_30674656428511)
#define D       128
#define MAX_N   100000
#define MAX_R   500

// Scratch (allocation-free rule: static __device__ globals)
__device__ float g_inv[MAX_N];          // 1/max(||z_i||, eps) per node
__device__ float g_cosp[MAX_R * D];     // cos(phase_rel)
__device__ int   g_is64;                // 1 if index buffers are int64, 0 if int32

// ---------------------------------------------------------------------------
// Kernel 0: detect index dtype. For int64 values < 2^31 the high 32-bit word
// of every element is zero (little-endian). For random int32 indices the odds
// of 32 consecutive zero words are ~0. One thread, runs once per launch.
// ---------------------------------------------------------------------------
__global__ void detect_kernel(const unsigned int* __restrict__ ei_words, int E) {
    int n = E < 32 ? E : 32;
    int is64 = 1;
    for (int i = 0; i < n; i++) {
        if (ei_words[2 * i + 1] != 0u) { is64 = 0; break; }
    }
    g_is64 = is64;
}

// ---------------------------------------------------------------------------
// Kernel 1: per-node inverse norm. One warp per node, float4 loads.
// ---------------------------------------------------------------------------
__global__ __launch_bounds__(256)
void norm_kernel(const float* __restrict__ z, int N) {
    int node = blockIdx.x * (blockDim.x >> 5) + (threadIdx.x >> 5);
    int lane = threadIdx.x & 31;
    if (node >= N) return;
    const float4* row = reinterpret_cast<const float4*>(z + (size_t)node * D);
    float4 v = row[lane];
    float ss = v.x * v.x + v.y * v.y + v.z * v.z + v.w * v.w;
    #pragma unroll
    for (int o = 16; o; o >>= 1)
        ss += __shfl_xor_sync(0xffffffffu, ss, o);
    if (lane == 0) {
        float n = sqrtf(ss);
        g_inv[node] = 1.0f / fmaxf(n, 1e-12f);
    }
}

// ---------------------------------------------------------------------------
// Kernel 2: cos table. R*D = 64000 elements, trivial.
// ---------------------------------------------------------------------------
__global__ __launch_bounds__(256)
void cos_kernel(const float* __restrict__ phase, int RD) {
    int i = blockIdx.x * blockDim.x + threadIdx.x;
    if (i < RD) g_cosp[i] = cosf(phase[i]);
}

// ---------------------------------------------------------------------------
// Index fetch that works for either int32 or int64 buffers (uniform branch).
// ---------------------------------------------------------------------------
__device__ __forceinline__ int idx_at(const void* p, size_t i, int is64) {
    if (is64) return (int)__ldg(&((const long long*)p)[i]);
    return __ldg(&((const int*)p)[i]);
}

// ---------------------------------------------------------------------------
// Kernel 3: warp per TWO edges (6 independent LDG.128 per lane -> MLP=6).
//   out[e] = inv[s]*inv[d] * sum_k z[s][k] * cosp[t][k] * z[d][k]
// z (51 MB) + cos table (256 KB) are L2-resident; gathers are L2 hits.
// ---------------------------------------------------------------------------
__global__ __launch_bounds__(256)
void edge_kernel(const float* __restrict__ z,
                 const void* __restrict__ edge_index,
                 const void* __restrict__ edge_type,
                 float* __restrict__ out, int E) {
    int warp = blockIdx.x * (blockDim.x >> 5) + (threadIdx.x >> 5);
    int lane = threadIdx.x & 31;
    int e0 = warp * 2;
    if (e0 >= E) return;
    bool have1 = (e0 + 1) < E;
    int e1 = have1 ? e0 + 1 : e0;
    int is64 = g_is64;

    int s0 = idx_at(edge_index, (size_t)e0, is64);
    int d0 = idx_at(edge_index, (size_t)E + e0, is64);
    int t0 = idx_at(edge_type,  (size_t)e0, is64);
    int s1 = idx_at(edge_index, (size_t)e1, is64);
    int d1 = idx_at(edge_index, (size_t)E + e1, is64);
    int t1 = idx_at(edge_type,  (size_t)e1, is64);

    const float4* zs0 = reinterpret_cast<const float4*>(z + (size_t)s0 * D);
    const float4* zd0 = reinterpret_cast<const float4*>(z + (size_t)d0 * D);
    const float4* cp0 = reinterpret_cast<const float4*>(g_cosp + t0 * D);
    const float4* zs1 = reinterpret_cast<const float4*>(z + (size_t)s1 * D);
    const float4* zd1 = reinterpret_cast<const float4*>(z + (size_t)d1 * D);
    const float4* cp1 = reinterpret_cast<const float4*>(g_cosp + t1 * D);

    // Issue all six 16B loads before consuming (MLP=6).
    float4 a0 = __ldg(&zs0[lane]);
    float4 b0 = __ldg(&zd0[lane]);
    float4 c0 = cp0[lane];
    float4 a1 = __ldg(&zs1[lane]);
    float4 b1 = __ldg(&zd1[lane]);
    float4 c1 = cp1[lane];

    float r0 = a0.x * c0.x * b0.x
             + a0.y * c0.y * b0.y
             + a0.z * c0.z * b0.z
             + a0.w * c0.w * b0.w;
    float r1 = a1.x * c1.x * b1.x
             + a1.y * c1.y * b1.y
             + a1.z * c1.z * b1.z
             + a1.w * c1.w * b1.w;

    #pragma unroll
    for (int o = 16; o; o >>= 1) {
        r0 += __shfl_xor_sync(0xffffffffu, r0, o);
        r1 += __shfl_xor_sync(0xffffffffu, r1, o);
    }

    if (lane == 0) {
        out[e0] = r0 * g_inv[s0] * g_inv[d0];
        if (have1)
            out[e1] = r1 * g_inv[s1] * g_inv[d1];
    }
}

// ---------------------------------------------------------------------------
// Launch. Inputs (metadata order): z[f32 N*D], edge_index[2*E int32 or int64],
// edge_type[E same dtype], phase_rel[f32 R*D]. Output: f32 [E].
// ---------------------------------------------------------------------------
extern "C" void kernel_launch(void* const* d_in, const int* in_sizes, int n_in,
                              void* d_out, int out_size) {
    const float* z  = (const float*)d_in[0];
    const void*  ei = d_in[1];
    const void*  et = d_in[2];
    const float* ph = (const float*)d_in[3];
    float* out = (float*)d_out;

    int N  = in_sizes[0] / D;
    int E  = in_sizes[2];
    int RD = in_sizes[3];
    if (E <= 0) return;

    detect_kernel<<<1, 1>>>((const unsigned int*)ei, E);
    norm_kernel<<<(N + 7) / 8, 256>>>(z, N);
    cos_kernel<<<(RD + 255) / 256, 256>>>(ph, RD);
    // 8 warps/block, 2 edges/warp -> 16 edges/block
    edge_kernel<<<(E + 15) / 16, 256>>>(z, ei, et, out, E);
}

// round 7
// speedup vs baseline: 1.2264x; 1.2264x over previous
#include <cuda_runtime.h>
#include <cuda_bf16.h>
#include <math.h>

// Problem constants (RotatEDecoder_30674656428511)
#define D       128
#define MAX_N   100000
#define MAX_R   500
#define FULL    0xffffffffu

// Scratch (allocation-free rule: static __device__ globals)
__device__ float g_inv[MAX_N];          // 1/max(||z_i||, eps) per node
__device__ float g_cosp[MAX_R * D];     // cos(phase_rel)
__device__ int   g_is64;                // 1 if index buffers are int64, 0 if int32

// ---------------------------------------------------------------------------
// Fused pre-pass: dtype detect (warp-parallel ballot, not a serial loop),
// cos table, per-node inverse norms. One launch instead of three.
// ---------------------------------------------------------------------------
__global__ __launch_bounds__(256)
void pre_kernel(const float* __restrict__ z, int N,
                const float* __restrict__ phase, int RD,
                const unsigned int* __restrict__ ei_words, int E) {
    // --- dtype detect: block 0, warp 0. int64 indices < 2^31 have zero high
    // words; 32 consecutive zero words from random int32 indices is ~impossible.
    if (blockIdx.x == 0 && threadIdx.x < 32) {
        int lane = threadIdx.x;
        unsigned int hi = (lane < E) ? ei_words[2 * lane + 1] : 0u;
        unsigned int any = __ballot_sync(FULL, hi != 0u);
        if (lane == 0) g_is64 = (any == 0u) ? 1 : 0;
    }

    // --- cos table (grid-stride; RD = 64000 << gridsize*256)
    int tid = blockIdx.x * blockDim.x + threadIdx.x;
    int nth = gridDim.x * blockDim.x;
    for (int i = tid; i < RD; i += nth)
        g_cosp[i] = cosf(phase[i]);

    // --- inverse norm: warp per node, float4 loads
    int node = blockIdx.x * (blockDim.x >> 5) + (threadIdx.x >> 5);
    int lane = threadIdx.x & 31;
    if (node < N) {
        float4 v = reinterpret_cast<const float4*>(z + (size_t)node * D)[lane];
        float ss = v.x * v.x + v.y * v.y + v.z * v.z + v.w * v.w;
        #pragma unroll
        for (int o = 16; o; o >>= 1)
            ss += __shfl_xor_sync(FULL, ss, o);
        if (lane == 0)
            g_inv[node] = 1.0f / fmaxf(sqrtf(ss), 1e-12f);
    }
}

// ---------------------------------------------------------------------------
// Edge kernel: warp per TWO edges.
//   out[e] = inv[s]*inv[d] * sum_k z[s][k] * cosp[t][k] * z[d][k]
// 6 independent LDG.128 per lane (MLP=6) against L2-resident z + L1-resident
// cos table. Vectorized index loads (pairs), hoisted g_inv loads, half-warp
// split reduction (7 shfls for both edges), single STG.64 result store.
// ---------------------------------------------------------------------------
__global__ __launch_bounds__(256)
void edge_kernel(const float* __restrict__ z,
                 const void* __restrict__ edge_index,
                 const void* __restrict__ edge_type,
                 float* __restrict__ out, int E) {
    int warp = blockIdx.x * (blockDim.x >> 5) + (threadIdx.x >> 5);
    int lane = threadIdx.x & 31;
    int e0 = warp * 2;
    if (e0 >= E) return;
    bool have1 = (e0 + 1) < E;
    int is64 = g_is64;

    int s0, d0, t0, s1, d1, t1;
    if (have1) {
        if (is64) {
            longlong2 sp = __ldg(&((const longlong2*)edge_index)[warp]);
            longlong2 dp = __ldg(&((const longlong2*)((const long long*)edge_index + E))[warp]);
            longlong2 tp = __ldg(&((const longlong2*)edge_type)[warp]);
            s0 = (int)sp.x; s1 = (int)sp.y;
            d0 = (int)dp.x; d1 = (int)dp.y;
            t0 = (int)tp.x; t1 = (int)tp.y;
        } else {
            int2 sp = __ldg(&((const int2*)edge_index)[warp]);
            int2 dp = __ldg(&((const int2*)((const int*)edge_index + E))[warp]);
            int2 tp = __ldg(&((const int2*)edge_type)[warp]);
            s0 = sp.x; s1 = sp.y;
            d0 = dp.x; d1 = dp.y;
            t0 = tp.x; t1 = tp.y;
        }
    } else {
        if (is64) {
            s0 = (int)__ldg(&((const long long*)edge_index)[e0]);
            d0 = (int)__ldg(&((const long long*)edge_index)[(size_t)E + e0]);
            t0 = (int)__ldg(&((const long long*)edge_type)[e0]);
        } else {
            s0 = __ldg(&((const int*)edge_index)[e0]);
            d0 = __ldg(&((const int*)edge_index)[(size_t)E + e0]);
            t0 = __ldg(&((const int*)edge_type)[e0]);
        }
        s1 = s0; d1 = d0; t1 = t0;
    }

    // Hoist scalar inv loads so their latency overlaps the FMA chain.
    // Lanes 0-15 fetch edge0's pair, lanes 16-31 edge1's (broadcast within half).
    int ss = (lane < 16) ? s0 : s1;
    int dd = (lane < 16) ? d0 : d1;
    float invp = __ldg(&g_inv[ss]) * __ldg(&g_inv[dd]);

    const float4* zs0 = reinterpret_cast<const float4*>(z + (size_t)s0 * D);
    const float4* zd0 = reinterpret_cast<const float4*>(z + (size_t)d0 * D);
    const float4* cp0 = reinterpret_cast<const float4*>(g_cosp + t0 * D);
    const float4* zs1 = reinterpret_cast<const float4*>(z + (size_t)s1 * D);
    const float4* zd1 = reinterpret_cast<const float4*>(z + (size_t)d1 * D);
    const float4* cp1 = reinterpret_cast<const float4*>(g_cosp + t1 * D);

    // Issue all six 16B loads before consuming (MLP=6).
    float4 a0 = __ldg(&zs0[lane]);
    float4 b0 = __ldg(&zd0[lane]);
    float4 c0 = cp0[lane];
    float4 a1 = __ldg(&zs1[lane]);
    float4 b1 = __ldg(&zd1[lane]);
    float4 c1 = cp1[lane];

    float r0 = a0.x * c0.x * b0.x
             + a0.y * c0.y * b0.y
             + a0.z * c0.z * b0.z
             + a0.w * c0.w * b0.w;
    float r1 = a1.x * c1.x * b1.x
             + a1.y * c1.y * b1.y
             + a1.z * c1.z * b1.z
             + a1.w * c1.w * b1.w;

    // Half-warp split reduction: fold across the 16-boundary, then one
    // 4-level butterfly reduces edge0 in the low half and edge1 in the high
    // half simultaneously. 7 shfls total instead of 10.
    float aa = r0 + __shfl_xor_sync(FULL, r0, 16);
    float bb = r1 + __shfl_xor_sync(FULL, r1, 16);
    float v = (lane < 16) ? aa : bb;
    #pragma unroll
    for (int o = 8; o; o >>= 1)
        v += __shfl_xor_sync(FULL, v, o);

    float scaled = v * invp;                    // valid on lanes 0 and 16
    float o1 = __shfl_sync(FULL, scaled, 16);   // edge1 result to lane 0

    if (lane == 0) {
        if (have1)
            *reinterpret_cast<float2*>(out + e0) = make_float2(scaled, o1);
        else
            out[e0] = scaled;
    }
}

// ---------------------------------------------------------------------------
// Launch. Inputs (metadata order): z[f32 N*D], edge_index[2*E int32 or int64],
// edge_type[E same dtype], phase_rel[f32 R*D]. Output: f32 [E].
// ---------------------------------------------------------------------------
extern "C" void kernel_launch(void* const* d_in, const int* in_sizes, int n_in,
                              void* d_out, int out_size) {
    const float* z  = (const float*)d_in[0];
    const void*  ei = d_in[1];
    const void*  et = d_in[2];
    const float* ph = (const float*)d_in[3];
    float* out = (float*)d_out;

    int N  = in_sizes[0] / D;
    int E  = in_sizes[2];
    int RD = in_sizes[3];
    if (E <= 0) return;

    pre_kernel<<<(N + 7) / 8, 256>>>(z, N, ph, RD, (const unsigned int*)ei, E);
    // 8 warps/block, 2 edges/warp -> 16 edges/block
    edge_kernel<<<(E + 15) / 16, 256>>>(z, ei, et, out, E);
}